// round 8
// baseline (speedup 1.0000x reference)
#include <cuda_runtime.h>

#define FULL 0xffffffffu

constexpr int B = 4096;
constexpr int K = 64;
constexpr int L = 128;
constexpr int E_DIM = 16;

__device__ float g_loss[B];
__device__ unsigned g_ctr = 0;

typedef unsigned long long u64;

__device__ __forceinline__ u64 pk(float lo, float hi) {
    u64 r; asm("mov.b64 %0,{%1,%2};" : "=l"(r) : "f"(lo), "f"(hi)); return r;
}
__device__ __forceinline__ void upk(u64 v, float& lo, float& hi) {
    asm("mov.b64 {%0,%1},%2;" : "=f"(lo), "=f"(hi) : "l"(v));
}
__device__ __forceinline__ u64 fma2(u64 a, u64 b, u64 c) {
    u64 d; asm("fma.rn.f32x2 %0,%1,%2,%3;" : "=l"(d) : "l"(a), "l"(b), "l"(c)); return d;
}
__device__ __forceinline__ u64 mul2(u64 a, u64 b) {
    u64 d; asm("mul.rn.f32x2 %0,%1,%2;" : "=l"(d) : "l"(a), "l"(b)); return d;
}

// Wavefront-pipelined pHMM forward, TWO time steps per wall-iteration.
// Two batch elements per warp (16-lane halves). Lane h owns states
// {4h..4h+3}; lane 15 shadows state 64. At wall-iteration w, lane h processes
// steps {2(w-h), 2(w-h)+1}, consuming lane h-1's exports for the SAME two
// steps (v3 = fM'[4h], fd4 = fD'[4h] at each step), produced last iteration.
// Per-lane power-of-2 exponent Ex; alignment factor af = 2^(E_{h-1}-E_h) is
// piecewise-constant between rescales (heads: odd w, every 4 steps) and is
// refreshed only there. af = 0 on lane 0 (absorbs the boundary zero).
// Transitions: M2M,M2I,M2D,I2M,I2I,D2M,D2D.

#define ITER2(WV, RESC, GUARD) do {                                            \
    float pA3 = __shfl_up_sync(FULL, v3A, 1, 16);                              \
    float pAf = __shfl_up_sync(FULL, fdA, 1, 16);                              \
    float pB3 = __shfl_up_sync(FULL, v3B, 1, 16);                              \
    float pBf = __shfl_up_sync(FULL, fdB, 1, 16);                              \
    int2 sy = *(const int2*)(rawp + 2 * (WV));   /* symbols lA, lA+1 (<<8) */  \
    float4 evA = *(const float4*)(epbh + sy.x);                                \
    float4 evB = *(const float4*)(epbh + sy.y);                                \
    float pv3aA = pA3 * af, pfdaA = pAf * af;                                  \
    float pv3aB = pB3 * af, pfdaB = pBf * af;                                  \
    /* ── step A: from committed state; fM64_old = v3B ── */                   \
    u64 prevAa = fma2(Amm_a, FMa, fma2(Aim_a, FIa, mul2(Adm_a, FDa)));         \
    u64 prevAb = fma2(Amm_b, FMb, fma2(Aim_b, FIb, mul2(Adm_b, FDb)));         \
    u64 nFIaA = fma2(AqMI_a, FMa, mul2(AqII_a, FIa));                          \
    u64 nFIbA = fma2(AqMI_b, FMb, mul2(AqII_b, FIb));                          \
    float nFI64A = fmaf(Aq64MI, v3B, Aq64II * FI64);                           \
    float qA0, qA1, qA2, qA3; upk(prevAa, qA0, qA1); upk(prevAb, qA2, qA3);    \
    float vA0 = evA.x * qA0, vA1 = evA.y * qA1, vA2 = evA.z * qA2;             \
    float nv3A = evA.w * qA3;                                                  \
    float fdA0 = pfdaA;                                                        \
    float fdA1 = fmaf(Add0, fdA0, Amd0 * pv3aA);                               \
    float fdA2 = fmaf(Add1, fdA1, Amd1 * vA0);                                 \
    float fdA3 = fmaf(Add2, fdA2, Amd2 * vA1);                                 \
    float nfdA4 = fmaf(Add3, fdA3, Amd3 * vA2);                                \
    u64 FMaA = pk(pv3aA, vA0), FMbA = pk(vA1, vA2);                            \
    u64 FDaA = pk(fdA0, fdA1), FDbA = pk(fdA2, fdA3);                          \
    /* ── step B: from step-A state; fM64_old = nv3A ── */                     \
    u64 prevBa = fma2(Amm_a, FMaA, fma2(Aim_a, nFIaA, mul2(Adm_a, FDaA)));     \
    u64 prevBb = fma2(Amm_b, FMbA, fma2(Aim_b, nFIbA, mul2(Adm_b, FDbA)));     \
    u64 nFIaB = fma2(AqMI_a, FMaA, mul2(AqII_a, nFIaA));                       \
    u64 nFIbB = fma2(AqMI_b, FMbA, mul2(AqII_b, nFIbA));                       \
    float nFI64B = fmaf(Aq64MI, nv3A, Aq64II * nFI64A);                        \
    float qB0, qB1, qB2, qB3; upk(prevBa, qB0, qB1); upk(prevBb, qB2, qB3);    \
    float vB0 = evB.x * qB0, vB1 = evB.y * qB1, vB2 = evB.z * qB2;             \
    float nv3B = evB.w * qB3;                                                  \
    float fdB0 = pfdaB;                                                        \
    float fdB1 = fmaf(Add0, fdB0, Amd0 * pv3aB);                               \
    float fdB2 = fmaf(Add1, fdB1, Amd1 * vB0);                                 \
    float fdB3 = fmaf(Add2, fdB2, Amd2 * vB1);                                 \
    float nfdB4 = fmaf(Add3, fdB3, Amd3 * vB2);                                \
    u64 nFMa = pk(pv3aB, vB0), nFMb = pk(vB1, vB2);                            \
    u64 nFDa = pk(fdB0, fdB1), nFDb = pk(fdB2, fdB3);                          \
    int exv = 0;                                                               \
    if (RESC) {                                                                \
        float m = fmaxf(fmaxf(pv3aB, vB0), fmaxf(vB1, vB2));                   \
        m = fmaxf(m, fmaxf(fmaxf(fdB0, fdB1), fmaxf(fdB2, fdB3)));             \
        float g0, g1, g2, g3; upk(nFIaB, g0, g1); upk(nFIbB, g2, g3);          \
        m = fmaxf(m, fmaxf(fmaxf(g0, g1), fmaxf(g2, g3)));                     \
        m = fmaxf(m, fmaxf(nv3A, nv3B));                                       \
        m = fmaxf(m, fmaxf(nfdA4, nfdB4));                                     \
        m = fmaxf(m, nFI64B);                                                  \
        exv = (int)((__float_as_uint(m) >> 23) & 255) - 127;                   \
        float sc = __uint_as_float((unsigned)(127 - exv) << 23);               \
        u64 s2 = pk(sc, sc);                                                   \
        nFMa = mul2(nFMa, s2); nFMb = mul2(nFMb, s2);                          \
        nFIaB = mul2(nFIaB, s2); nFIbB = mul2(nFIbB, s2);                      \
        nFDa = mul2(nFDa, s2); nFDb = mul2(nFDb, s2);                          \
        nv3A *= sc; nv3B *= sc; nfdA4 *= sc; nfdB4 *= sc; nFI64B *= sc;        \
    }                                                                          \
    if (GUARD) {                                                               \
        bool act = (unsigned)((WV) - h) < 64u;   /* pair index 0..63 */        \
        FMa = act ? nFMa : FMa;   FMb = act ? nFMb : FMb;                      \
        FIa = act ? nFIaB : FIa;  FIb = act ? nFIbB : FIb;                     \
        FDa = act ? nFDa : FDa;   FDb = act ? nFDb : FDb;                      \
        FI64 = act ? nFI64B : FI64;                                            \
        v3A = act ? nv3A : v3A;   v3B = act ? nv3B : v3B;                      \
        fdA = act ? nfdA4 : fdA;  fdB = act ? nfdB4 : fdB;                     \
        Ex = act ? (Ex + exv) : Ex;                                            \
    } else {                                                                   \
        FMa = nFMa; FMb = nFMb; FIa = nFIaB; FIb = nFIbB;                      \
        FDa = nFDa; FDb = nFDb; FI64 = nFI64B;                                 \
        v3A = nv3A; v3B = nv3B; fdA = nfdA4; fdB = nfdB4; Ex += exv;           \
    }                                                                          \
    if (RESC) {   /* refresh alignment factor (valid until next head) */       \
        int pE = __shfl_up_sync(FULL, Ex, 1, 16);                              \
        int dE = pE - Ex; dE = max(-126, min(126, dE));                        \
        af = (h == 0) ? 0.0f                                                   \
                      : __uint_as_float((unsigned)(127 + dE) << 23);           \
    }                                                                          \
} while (0)

__global__ __launch_bounds__(64) void phmm_kernel(
    const int*   __restrict__ x,
    const float* __restrict__ a,
    const float* __restrict__ e,
    const float* __restrict__ mus,
    const float* __restrict__ lvs,
    float*       __restrict__ out)
{
    const int lane = threadIdx.x & 31;
    const int half = lane >> 4;
    const int h    = lane & 15;
    const int wIn  = threadIdx.x >> 5;
    const int warp = blockIdx.x * 2 + wIn;
    const int b = 2 * warp + half;

    __shared__ float4 sh_e[2 * 2 * 4 * 16];  // [warp][half][symbol][hlane]
    __shared__ int    sh_x[2 * 2 * 192];     // padded symbols (×256 pre-scaled)
    __shared__ float sw[2];
    __shared__ unsigned s_rank;

    const float* ab = a + (size_t)b * (K + 1) * 7;
    const int k0 = 4 * h;
    const float* A0 = ab + (k0 + 0) * 7;
    const float* A1 = ab + (k0 + 1) * 7;
    const float* A2 = ab + (k0 + 2) * 7;
    const float* A3 = ab + (k0 + 3) * 7;

    u64 Amm_a  = pk(__expf(A0[0]), __expf(A1[0]));
    u64 Amm_b  = pk(__expf(A2[0]), __expf(A3[0]));
    u64 AqMI_a = pk(0.25f * __expf(A0[1]), 0.25f * __expf(A1[1]));
    u64 AqMI_b = pk(0.25f * __expf(A2[1]), 0.25f * __expf(A3[1]));
    float Amd0 = __expf(A0[2]), Amd1 = __expf(A1[2]);
    float Amd2 = __expf(A2[2]), Amd3 = __expf(A3[2]);
    u64 Aim_a  = pk(__expf(A0[3]), __expf(A1[3]));
    u64 Aim_b  = pk(__expf(A2[3]), __expf(A3[3]));
    u64 AqII_a = pk(0.25f * __expf(A0[4]), 0.25f * __expf(A1[4]));
    u64 AqII_b = pk(0.25f * __expf(A2[4]), 0.25f * __expf(A3[4]));
    u64 Adm_a  = pk(__expf(A0[5]), __expf(A1[5]));
    u64 Adm_b  = pk(__expf(A2[5]), __expf(A3[5]));
    float Add0 = __expf(A0[6]), Add1 = __expf(A1[6]);
    float Add2 = __expf(A2[6]), Add3 = __expf(A3[6]);

    // Segment coefficients for the one-time init scan.
    float c1 = Add3 * Add2;
    float c0 = c1 * Add1;
    float segB = c0 * Add0;

    const float* a64 = ab + K * 7;
    float A64mm  = __expf(a64[0]);
    float Aq64MI = 0.25f * __expf(a64[1]);
    float A64im  = __expf(a64[3]);
    float Aq64II = 0.25f * __expf(a64[4]);
    float A64dm  = __expf(a64[5]);

    // Emission LUT (conflict-free LDS.128): epb[sym*16+h] = exp(e[4h..4h+3][sym])
    const float4* e4 = (const float4*)(e + (size_t)b * K * 4);
    float4 e0 = e4[k0], e1 = e4[k0 + 1], e2 = e4[k0 + 2], e3 = e4[k0 + 3];
    float4* epb = sh_e + (size_t)((wIn * 2 + half) * 4) * 16;
    epb[0 * 16 + h] = make_float4(__expf(e0.x), __expf(e1.x), __expf(e2.x), __expf(e3.x));
    epb[1 * 16 + h] = make_float4(__expf(e0.y), __expf(e1.y), __expf(e2.y), __expf(e3.y));
    epb[2 * 16 + h] = make_float4(__expf(e0.z), __expf(e1.z), __expf(e2.z), __expf(e3.z));
    epb[3 * 16 + h] = make_float4(__expf(e0.w), __expf(e1.w), __expf(e2.w), __expf(e3.w));
    const char* epbh = (const char*)epb + h * 16;

    // Symbols to shared, pre-scaled by 256 (LUT byte offset), padded 32
    // front/back so the skewed int2 fetch never clamps.
    const int4* x4 = (const int4*)(x + (size_t)b * L);
    int* xr = sh_x + (wIn * 2 + half) * 192;
    {
        int4 xa = x4[h], xb = x4[h + 16];
        xr[2 * h] = 0; xr[2 * h + 1] = 0;
        xr[160 + 2 * h] = 0; xr[160 + 2 * h + 1] = 0;
        xr[32 + 4 * h + 0] = xa.x << 8;
        xr[32 + 4 * h + 1] = xa.y << 8;
        xr[32 + 4 * h + 2] = xa.z << 8;
        xr[32 + 4 * h + 3] = xa.w << 8;
        xr[96 + 4 * h + 0] = xb.x << 8;
        xr[96 + 4 * h + 1] = xb.y << 8;
        xr[96 + 4 * h + 2] = xb.z << 8;
        xr[96 + 4 * h + 3] = xb.w << 8;
    }
    const int* rawp = xr + 32 - 2 * h;   // rawp[2w] = x[2(w-h)] << 8

    // One-time Kogge-Stone weights + init fD chain.
    float Bp0, Bp1, Bp2, Bp3;
    {
        float Bacc = segB;
        Bp0 = (h >= 1) ? Bacc : 0.0f;
        float o = __shfl_up_sync(FULL, Bacc, 1, 16); if (h >= 1) Bacc *= o;
        Bp1 = (h >= 2) ? Bacc : 0.0f;
        o = __shfl_up_sync(FULL, Bacc, 2, 16); if (h >= 2) Bacc *= o;
        Bp2 = (h >= 4) ? Bacc : 0.0f;
        o = __shfl_up_sync(FULL, Bacc, 4, 16); if (h >= 4) Bacc *= o;
        Bp3 = (h >= 8) ? Bacc : 0.0f;
    }

    // Initial state: fM[0]=1 rest 0; fI=0; fD via init scan.
    u64 FMa = pk((h == 0) ? 1.0f : 0.0f, 0.0f);
    u64 FMb = pk(0.0f, 0.0f);
    u64 FIa = pk(0.0f, 0.0f), FIb = pk(0.0f, 0.0f);
    float FI64 = 0.0f;
    float v3A = 0.0f, v3B = 0.0f;   // step exports: fM'[4h+4] at steps lA, lB
    float fdA = 0.0f, fdB = 0.0f;   // step exports: fD'[4h+4] at steps lA, lB
    int Ex = 0;
    float af = (h == 0) ? 0.0f : 1.0f;
    u64 FDa, FDb;
    {
        float fm0 = (h == 0) ? 1.0f : 0.0f;
        float u0 = Amd0 * fm0;
        float al = c0 * u0;
        float t_;
        t_ = __shfl_up_sync(FULL, al, 1, 16); al = fmaf(Bp0, t_, al);
        t_ = __shfl_up_sync(FULL, al, 2, 16); al = fmaf(Bp1, t_, al);
        t_ = __shfl_up_sync(FULL, al, 4, 16); al = fmaf(Bp2, t_, al);
        t_ = __shfl_up_sync(FULL, al, 8, 16); al = fmaf(Bp3, t_, al);
        float carry = __shfl_up_sync(FULL, al, 1, 16);
        if (h == 0) carry = 0.0f;
        float fd0 = carry;
        float fd1 = fmaf(Add0, fd0, u0);
        float fd2 = Add1 * fd1;
        float fd3 = Add2 * fd2;
        FDa = pk(fd0, fd1); FDb = pk(fd2, fd3);
    }

    __syncthreads();             // shared LUTs + symbols visible

    // ── ramp-in: w = 0..14 (guarded); rescale heads at odd w ──
    #pragma unroll 1
    for (int w = 0; w < 15; ++w) {
        bool rs = (w & 1) == 1;
        ITER2(w, rs, true);
    }
    // ── steady: w = 15..63 (all lanes active) ──
    #pragma unroll 1
    for (int wb = 15; wb < 63; wb += 2) {
        ITER2(wb,     true,  false);     // odd w: head
        ITER2(wb + 1, false, false);
    }
    ITER2(63, true, false);
    // ── ramp-out: w = 64..78 (guarded) ──
    #pragma unroll 1
    for (int w = 64; w < 79; ++w) {
        bool rs = (w & 1) == 1;
        ITER2(w, rs, true);
    }

    // KLD: each hlane handles one latent dim for its batch.
    float kt;
    {
        float mu = mus[(size_t)b * E_DIM + h];
        float lv = lvs[(size_t)b * E_DIM + h];
        kt = 1.0f + lv - mu * mu - __expf(lv);
    }
    kt += __shfl_xor_sync(FULL, kt, 8, 16);
    kt += __shfl_xor_sync(FULL, kt, 4, 16);
    kt += __shfl_xor_sync(FULL, kt, 2, 16);
    kt += __shfl_xor_sync(FULL, kt, 1, 16);
    float kld = -0.5f * kt;

    if (h == 15) {
        // Final (step 127): fM[64]=v3B, fI[64]=FI64, fD[64]=fdB at scale 2^Ex.
        float fin = fmaf(A64mm, v3B, fmaf(A64im, FI64, A64dm * fdB));
        g_loss[b] = -(logf(fin) + (float)Ex * 0.69314718055994531f) + kld;
    }

    // ── Fused deterministic final reduction (last-block-done) ──
    __threadfence();
    __syncthreads();
    if (threadIdx.x == 0) s_rank = atomicAdd(&g_ctr, 1);
    __syncthreads();
    if (s_rank == gridDim.x - 1) {
        __threadfence();
        float v = 0.0f;
        #pragma unroll
        for (int i = 0; i < B / 64; ++i)
            v += __ldcg(&g_loss[threadIdx.x + i * 64]);
        v += __shfl_xor_sync(FULL, v, 16);
        v += __shfl_xor_sync(FULL, v, 8);
        v += __shfl_xor_sync(FULL, v, 4);
        v += __shfl_xor_sync(FULL, v, 2);
        v += __shfl_xor_sync(FULL, v, 1);
        if (lane == 0) sw[wIn] = v;
        __syncthreads();
        if (threadIdx.x == 0) {
            out[0] = (sw[0] + sw[1]) * (1.0f / (float)B);
            g_ctr = 0;   // reset for next graph replay
        }
    }
}

extern "C" void kernel_launch(void* const* d_in, const int* in_sizes, int n_in,
                              void* d_out, int out_size)
{
    const int*   x   = (const int*)d_in[0];
    const float* a   = (const float*)d_in[1];
    const float* e   = (const float*)d_in[2];
    const float* mus = (const float*)d_in[3];
    const float* lvs = (const float*)d_in[4];

    // 1024 blocks × 2 warps × 2 batches/warp = 4096 batch elements.
    phmm_kernel<<<B / 4, 64>>>(x, a, e, mus, lvs, (float*)d_out);
}

// round 9
// speedup vs baseline: 1.6646x; 1.6646x over previous
#include <cuda_runtime.h>

#define FULL 0xffffffffu

constexpr int B = 4096;
constexpr int K = 64;
constexpr int L = 128;
constexpr int E_DIM = 16;

__device__ float g_loss[B];
__device__ unsigned g_ctr = 0;

// Wavefront-pipelined pHMM forward, one time step per wall-iteration.
// Two batch elements per warp (16-lane halves). Lane h owns states
// {4h..4h+3}; lane 15 shadows state 64. At wall-iteration w, lane h processes
// its step l = w - h, consuming lane h-1's same-step exports (v3 = fM'[4h],
// fd4 = fD'[4h]) produced at iteration w-1. Per-lane power-of-2 exponent Ex;
// alignment factor af = 2^(E_{h-1}-E_h) is piecewise-constant between rescale
// heads ((w & 3) == 3) and refreshed only there; af = 0 on lane 0 absorbs the
// boundary zero. Transitions: M2M,M2I,M2D,I2M,I2I,D2M,D2D.

#define ITER(WV, RESC, GUARD) do {                                             \
    float pv3 = __shfl_up_sync(FULL, v3x, 1, 16);                              \
    float pfd = __shfl_up_sync(FULL, fd4x, 1, 16);                             \
    float4 ev = *(const float4*)(epbh + nsymB);  /* conflict-free LDS.128 */   \
    nsymB = rawp[WV];                         /* prefetch next step (x<<8) */  \
    float pv3a = pv3 * af;                                                     \
    float pfda = pfd * af;                                                     \
    float q0 = fmaf(Amm0, FM0, fmaf(Aim0, FI0, Adm0 * FD0));                   \
    float q1 = fmaf(Amm1, FM1, fmaf(Aim1, FI1, Adm1 * FD1));                   \
    float q2 = fmaf(Amm2, FM2, fmaf(Aim2, FI2, Adm2 * FD2));                   \
    float q3 = fmaf(Amm3, FM3, fmaf(Aim3, FI3, Adm3 * FD3));                   \
    float nI0 = fmaf(AqMI0, FM0, AqII0 * FI0);                                 \
    float nI1 = fmaf(AqMI1, FM1, AqII1 * FI1);                                 \
    float nI2 = fmaf(AqMI2, FM2, AqII2 * FI2);                                 \
    float nI3 = fmaf(AqMI3, FM3, AqII3 * FI3);                                 \
    float nFI64 = fmaf(Aq64MI, v3x, Aq64II * FI64);                            \
    float v0 = ev.x * q0, v1 = ev.y * q1, v2 = ev.z * q2, nv3 = ev.w * q3;     \
    float fd0 = pfda;                                                          \
    float fd1 = fmaf(Add0, fd0, Amd0 * pv3a);                                  \
    float fd2 = fmaf(Add1, fd1, Amd1 * v0);                                    \
    float fd3 = fmaf(Add2, fd2, Amd2 * v1);                                    \
    float nfd4 = fmaf(Add3, fd3, Amd3 * v2);                                   \
    float nM0 = pv3a, nM1 = v0, nM2 = v1, nM3 = v2;                            \
    int exv = 0;                                                               \
    if (RESC) {                                                                \
        float m = fmaxf(fmaxf(nM0, nM1), fmaxf(nM2, nM3));                     \
        m = fmaxf(m, fmaxf(fmaxf(nI0, nI1), fmaxf(nI2, nI3)));                 \
        m = fmaxf(m, fmaxf(fmaxf(fd0, fd1), fmaxf(fd2, fd3)));                 \
        m = fmaxf(m, fmaxf(nv3, fmaxf(nfd4, nFI64)));                         \
        exv = (int)((__float_as_uint(m) >> 23) & 255) - 127;                   \
        float sc = __uint_as_float((unsigned)(127 - exv) << 23);               \
        nM0 *= sc; nM1 *= sc; nM2 *= sc; nM3 *= sc;                            \
        nI0 *= sc; nI1 *= sc; nI2 *= sc; nI3 *= sc;                            \
        fd0 *= sc; fd1 *= sc; fd2 *= sc; fd3 *= sc;                            \
        nv3 *= sc; nfd4 *= sc; nFI64 *= sc;                                    \
    }                                                                          \
    if (GUARD) {                                                               \
        bool act = (unsigned)((WV) - h) < 128u;                                \
        FM0 = act ? nM0 : FM0; FM1 = act ? nM1 : FM1;                          \
        FM2 = act ? nM2 : FM2; FM3 = act ? nM3 : FM3;                          \
        FI0 = act ? nI0 : FI0; FI1 = act ? nI1 : FI1;                          \
        FI2 = act ? nI2 : FI2; FI3 = act ? nI3 : FI3;                          \
        FD0 = act ? fd0 : FD0; FD1 = act ? fd1 : FD1;                          \
        FD2 = act ? fd2 : FD2; FD3 = act ? fd3 : FD3;                          \
        FI64 = act ? nFI64 : FI64;                                             \
        v3x  = act ? nv3  : v3x;                                               \
        fd4x = act ? nfd4 : fd4x;                                              \
        Ex   = act ? (Ex + exv) : Ex;                                          \
    } else {                                                                   \
        FM0 = nM0; FM1 = nM1; FM2 = nM2; FM3 = nM3;                            \
        FI0 = nI0; FI1 = nI1; FI2 = nI2; FI3 = nI3;                            \
        FD0 = fd0; FD1 = fd1; FD2 = fd2; FD3 = fd3;                            \
        FI64 = nFI64; v3x = nv3; fd4x = nfd4; Ex += exv;                       \
    }                                                                          \
    if (RESC) {   /* refresh alignment factor (valid until next head) */       \
        int pE = __shfl_up_sync(FULL, Ex, 1, 16);                              \
        int dE = pE - Ex; dE = max(-126, min(126, dE));                        \
        af = (h == 0) ? 0.0f                                                   \
                      : __uint_as_float((unsigned)(127 + dE) << 23);           \
    }                                                                          \
} while (0)

__global__ __launch_bounds__(64) void phmm_kernel(
    const int*   __restrict__ x,
    const float* __restrict__ a,
    const float* __restrict__ e,
    const float* __restrict__ mus,
    const float* __restrict__ lvs,
    float*       __restrict__ out)
{
    const int lane = threadIdx.x & 31;
    const int half = lane >> 4;
    const int h    = lane & 15;
    const int wIn  = threadIdx.x >> 5;
    const int warp = blockIdx.x * 2 + wIn;
    const int b = 2 * warp + half;

    __shared__ float4 sh_e[2 * 2 * 4 * 16];  // [warp][half][symbol][hlane]
    __shared__ int    sh_x[2 * 2 * 160];     // padded symbols (×256 pre-scaled)
    __shared__ float sw[2];
    __shared__ unsigned s_rank;

    const float* ab = a + (size_t)b * (K + 1) * 7;
    const int k0 = 4 * h;
    const float* A0 = ab + (k0 + 0) * 7;
    const float* A1 = ab + (k0 + 1) * 7;
    const float* A2 = ab + (k0 + 2) * 7;
    const float* A3 = ab + (k0 + 3) * 7;

    float Amm0 = __expf(A0[0]), Amm1 = __expf(A1[0]);
    float Amm2 = __expf(A2[0]), Amm3 = __expf(A3[0]);
    float AqMI0 = 0.25f * __expf(A0[1]), AqMI1 = 0.25f * __expf(A1[1]);
    float AqMI2 = 0.25f * __expf(A2[1]), AqMI3 = 0.25f * __expf(A3[1]);
    float Amd0 = __expf(A0[2]), Amd1 = __expf(A1[2]);
    float Amd2 = __expf(A2[2]), Amd3 = __expf(A3[2]);
    float Aim0 = __expf(A0[3]), Aim1 = __expf(A1[3]);
    float Aim2 = __expf(A2[3]), Aim3 = __expf(A3[3]);
    float AqII0 = 0.25f * __expf(A0[4]), AqII1 = 0.25f * __expf(A1[4]);
    float AqII2 = 0.25f * __expf(A2[4]), AqII3 = 0.25f * __expf(A3[4]);
    float Adm0 = __expf(A0[5]), Adm1 = __expf(A1[5]);
    float Adm2 = __expf(A2[5]), Adm3 = __expf(A3[5]);
    float Add0 = __expf(A0[6]), Add1 = __expf(A1[6]);
    float Add2 = __expf(A2[6]), Add3 = __expf(A3[6]);

    // Segment coefficients for the one-time init scan.
    float c1 = Add3 * Add2;
    float c0 = c1 * Add1;
    float segB = c0 * Add0;

    const float* a64 = ab + K * 7;
    float A64mm  = __expf(a64[0]);
    float Aq64MI = 0.25f * __expf(a64[1]);
    float A64im  = __expf(a64[3]);
    float Aq64II = 0.25f * __expf(a64[4]);
    float A64dm  = __expf(a64[5]);

    // Emission LUT (conflict-free LDS.128): epb[sym*16+h] = exp(e[4h..4h+3][sym])
    const float4* e4 = (const float4*)(e + (size_t)b * K * 4);
    float4 e0 = e4[k0], e1 = e4[k0 + 1], e2 = e4[k0 + 2], e3 = e4[k0 + 3];
    float4* epb = sh_e + (size_t)((wIn * 2 + half) * 4) * 16;
    epb[0 * 16 + h] = make_float4(__expf(e0.x), __expf(e1.x), __expf(e2.x), __expf(e3.x));
    epb[1 * 16 + h] = make_float4(__expf(e0.y), __expf(e1.y), __expf(e2.y), __expf(e3.y));
    epb[2 * 16 + h] = make_float4(__expf(e0.z), __expf(e1.z), __expf(e2.z), __expf(e3.z));
    epb[3 * 16 + h] = make_float4(__expf(e0.w), __expf(e1.w), __expf(e2.w), __expf(e3.w));
    const char* epbh = (const char*)epb + h * 16;

    // Symbols to shared, pre-scaled by 256 (LUT byte offset), padded 16
    // front/back so the skewed prefetch never clamps.
    const int4* x4 = (const int4*)(x + (size_t)b * L);
    int* xr = sh_x + (wIn * 2 + half) * 160;
    {
        int4 xa = x4[h], xb = x4[h + 16];
        xr[h] = 0; xr[144 + h] = 0;
        xr[16 + 4 * h + 0] = xa.x << 8;
        xr[16 + 4 * h + 1] = xa.y << 8;
        xr[16 + 4 * h + 2] = xa.z << 8;
        xr[16 + 4 * h + 3] = xa.w << 8;
        xr[80 + 4 * h + 0] = xb.x << 8;
        xr[80 + 4 * h + 1] = xb.y << 8;
        xr[80 + 4 * h + 2] = xb.z << 8;
        xr[80 + 4 * h + 3] = xb.w << 8;
    }
    const int* rawp = xr + 17 - h;   // rawp[w] = x[w - h + 1] << 8

    // One-time Kogge-Stone weights + init fD chain.
    float Bp0, Bp1, Bp2, Bp3;
    {
        float Bacc = segB;
        Bp0 = (h >= 1) ? Bacc : 0.0f;
        float o = __shfl_up_sync(FULL, Bacc, 1, 16); if (h >= 1) Bacc *= o;
        Bp1 = (h >= 2) ? Bacc : 0.0f;
        o = __shfl_up_sync(FULL, Bacc, 2, 16); if (h >= 2) Bacc *= o;
        Bp2 = (h >= 4) ? Bacc : 0.0f;
        o = __shfl_up_sync(FULL, Bacc, 4, 16); if (h >= 4) Bacc *= o;
        Bp3 = (h >= 8) ? Bacc : 0.0f;
    }

    // Initial state: fM[0]=1 rest 0; fI=0; fD via init scan.
    float FM0 = (h == 0) ? 1.0f : 0.0f;
    float FM1 = 0.0f, FM2 = 0.0f, FM3 = 0.0f;
    float FI0 = 0.0f, FI1 = 0.0f, FI2 = 0.0f, FI3 = 0.0f;
    float FI64 = 0.0f;
    float v3x = 0.0f;            // export fM'[4h+4] / fM[64] shadow
    float fd4x;                  // export fD'[4h+4] / fD[64] shadow
    int Ex = 0;
    float af = (h == 0) ? 0.0f : 1.0f;
    float FD0, FD1, FD2, FD3;
    {
        float u0 = Amd0 * FM0;
        float al = c0 * u0;
        float t_;
        t_ = __shfl_up_sync(FULL, al, 1, 16); al = fmaf(Bp0, t_, al);
        t_ = __shfl_up_sync(FULL, al, 2, 16); al = fmaf(Bp1, t_, al);
        t_ = __shfl_up_sync(FULL, al, 4, 16); al = fmaf(Bp2, t_, al);
        t_ = __shfl_up_sync(FULL, al, 8, 16); al = fmaf(Bp3, t_, al);
        float carry = __shfl_up_sync(FULL, al, 1, 16);
        if (h == 0) carry = 0.0f;
        FD0 = carry;
        FD1 = fmaf(Add0, FD0, u0);
        FD2 = Add1 * FD1;
        FD3 = Add2 * FD2;
        fd4x = al;
    }

    __syncthreads();             // shared LUTs + symbols visible

    int nsymB = rawp[h - 1];     // lane's first symbol: x[0] << 8

    // ── ramp-in: w = 0..14 (guarded); rescale heads at (w & 3) == 3 ──
    #pragma unroll 1
    for (int w = 0; w < 15; ++w) {
        bool rs = (w & 3) == 3;
        ITER(w, rs, true);
    }
    // ── steady: w = 15..126 (all lanes active); head at group start ──
    #pragma unroll 1
    for (int wb = 15; wb < 127; wb += 4) {
        ITER(wb,     true,  false);     // wb ≡ 3 (mod 4)
        ITER(wb + 1, false, false);
        ITER(wb + 2, false, false);
        ITER(wb + 3, false, false);
    }
    ITER(127, true, false);             // 127 & 3 == 3
    // ── ramp-out: w = 128..142 (guarded) ──
    #pragma unroll 1
    for (int w = 128; w < 143; ++w) {
        bool rs = (w & 3) == 3;
        ITER(w, rs, true);
    }

    // KLD: each hlane handles one latent dim for its batch.
    float kt;
    {
        float mu = mus[(size_t)b * E_DIM + h];
        float lv = lvs[(size_t)b * E_DIM + h];
        kt = 1.0f + lv - mu * mu - __expf(lv);
    }
    kt += __shfl_xor_sync(FULL, kt, 8, 16);
    kt += __shfl_xor_sync(FULL, kt, 4, 16);
    kt += __shfl_xor_sync(FULL, kt, 2, 16);
    kt += __shfl_xor_sync(FULL, kt, 1, 16);
    float kld = -0.5f * kt;

    if (h == 15) {
        // fM[64]=v3x, fI[64]=FI64, fD[64]=fd4x at scale 2^Ex.
        float fin = fmaf(A64mm, v3x, fmaf(A64im, FI64, A64dm * fd4x));
        g_loss[b] = -(logf(fin) + (float)Ex * 0.69314718055994531f) + kld;
    }

    // ── Fused deterministic final reduction (last-block-done) ──
    __threadfence();
    __syncthreads();
    if (threadIdx.x == 0) s_rank = atomicAdd(&g_ctr, 1);
    __syncthreads();
    if (s_rank == gridDim.x - 1) {
        __threadfence();
        float v = 0.0f;
        #pragma unroll
        for (int i = 0; i < B / 64; ++i)
            v += __ldcg(&g_loss[threadIdx.x + i * 64]);
        v += __shfl_xor_sync(FULL, v, 16);
        v += __shfl_xor_sync(FULL, v, 8);
        v += __shfl_xor_sync(FULL, v, 4);
        v += __shfl_xor_sync(FULL, v, 2);
        v += __shfl_xor_sync(FULL, v, 1);
        if (lane == 0) sw[wIn] = v;
        __syncthreads();
        if (threadIdx.x == 0) {
            out[0] = (sw[0] + sw[1]) * (1.0f / (float)B);
            g_ctr = 0;   // reset for next graph replay
        }
    }
}

extern "C" void kernel_launch(void* const* d_in, const int* in_sizes, int n_in,
                              void* d_out, int out_size)
{
    const int*   x   = (const int*)d_in[0];
    const float* a   = (const float*)d_in[1];
    const float* e   = (const float*)d_in[2];
    const float* mus = (const float*)d_in[3];
    const float* lvs = (const float*)d_in[4];

    // 1024 blocks × 2 warps × 2 batches/warp = 4096 batch elements.
    phmm_kernel<<<B / 4, 64>>>(x, a, e, mus, lvs, (float*)d_out);
}